// round 3
// baseline (speedup 1.0000x reference)
#include <cuda_runtime.h>

#define BB   8192
#define CC   2514
#define NN   2513      // number of foreground classes
#define TPB  256
#define P_EXP 0.8f
#define Q_EXP 2.0f
#define LOG_EPS -4.6051701859880914f   // log(0.01)
#define NEG_BIG -1e30f

__device__ int   g_hist[NN];
__device__ int   g_labels[BB];
__device__ float g_lc[NN];
__device__ float g_row_out[BB];

// ---------------------------------------------------------------------------
__global__ void k_zero_hist() {
    int i = blockIdx.x * blockDim.x + threadIdx.x;
    if (i < NN) g_hist[i] = 0;
}

// One block per row: find the one-hot label position, histogram fg labels.
__global__ void k_labels(const float* __restrict__ t) {
    int row = blockIdx.x;
    const float2* tr = reinterpret_cast<const float2*>(t + (size_t)row * CC);
    __shared__ int s_label;
    if (threadIdx.x == 0) s_label = 0;
    __syncthreads();
    // CC = 2514 -> 1257 float2 per row (rows are 8B aligned: 2514*4 % 8 == 0)
    for (int i = threadIdx.x; i < CC / 2; i += TPB) {
        float2 v = tr[i];
        if (v.x > 0.f) s_label = 2 * i;
        if (v.y > 0.f) s_label = 2 * i + 1;
    }
    __syncthreads();
    if (threadIdx.x == 0) {
        int l = s_label;
        g_labels[row] = l;
        if (l > 0) atomicAdd(&g_hist[l - 1], 1);
    }
}

// lc[j] = log(max(cum_samples[j] + count[j], 1))
__global__ void k_lc(const float* __restrict__ cum_samples) {
    int i = blockIdx.x * blockDim.x + threadIdx.x;
    if (i < NN) {
        float c = cum_samples[i] + (float)g_hist[i];
        c = fmaxf(c, 1.0f);
        g_lc[i] = __logf(c);
    }
}

// ---------------------------------------------------------------------------
__device__ __forceinline__ float blockMax(float v, float* sh) {
    #pragma unroll
    for (int o = 16; o > 0; o >>= 1)
        v = fmaxf(v, __shfl_xor_sync(0xffffffffu, v, o));
    if ((threadIdx.x & 31) == 0) sh[threadIdx.x >> 5] = v;
    __syncthreads();
    if (threadIdx.x < 32) {
        float r = (threadIdx.x < (TPB / 32)) ? sh[threadIdx.x] : NEG_BIG;
        #pragma unroll
        for (int o = 4; o > 0; o >>= 1)
            r = fmaxf(r, __shfl_xor_sync(0xffffffffu, r, o));
        if (threadIdx.x == 0) sh[0] = r;
    }
    __syncthreads();
    float r = sh[0];
    __syncthreads();   // allow sh reuse by the next reduction
    return r;
}

__device__ __forceinline__ float blockSum(float v, float* sh) {
    #pragma unroll
    for (int o = 16; o > 0; o >>= 1)
        v += __shfl_xor_sync(0xffffffffu, v, o);
    if ((threadIdx.x & 31) == 0) sh[threadIdx.x >> 5] = v;
    __syncthreads();
    if (threadIdx.x < 32) {
        float r = (threadIdx.x < (TPB / 32)) ? sh[threadIdx.x] : 0.f;
        #pragma unroll
        for (int o = 4; o > 0; o >>= 1)
            r += __shfl_xor_sync(0xffffffffu, r, o);
        if (threadIdx.x == 0) sh[0] = r;
    }
    __syncthreads();
    float r = sh[0];
    __syncthreads();
    return r;
}

// One block per row: full seesaw loss for that row, all in registers/log-domain.
__global__ void __launch_bounds__(TPB) k_row(const float* __restrict__ x) {
    const int row = blockIdx.x;
    const int tid = threadIdx.x;
    const float* xr = x + (size_t)row * CC + 1;   // foreground logits, NN of them

    __shared__ float sh[8];
    __shared__ float sh_b[2];

    const int K = 10;                              // ceil(2513/256)
    float xv[K];

    float m = NEG_BIG;
    #pragma unroll
    for (int k = 0; k < K; k++) {
        int j = tid + k * TPB;
        float v = (j < NN) ? __ldg(xr + j) : NEG_BIG;
        xv[k] = v;
        m = fmaxf(m, v);
    }
    m = blockMax(m, sh);

    float s = 0.f;
    #pragma unroll
    for (int k = 0; k < K; k++) {
        int j = tid + k * TPB;
        if (j < NN) s += __expf(xv[k] - m);
    }
    float S = blockSum(s, sh);

    int label = g_labels[row];
    if (label == 0) {                  // background row: excluded from loss
        if (tid == 0) g_row_out[row] = 0.f;
        return;
    }

    if (tid == 0) {
        sh_b[0] = xr[label - 1];       // x at the positive class
        sh_b[1] = g_lc[label - 1];     // log cum_c at the positive class
    }
    __syncthreads();
    float xl   = sh_b[0];
    float lc_l = sh_b[1];

    float base = m + __logf(S);                    // logsumexp(x)
    float ls   = fmaxf(xl - base, LOG_EPS);        // log(max(self_score, EPS))

    float m2 = NEG_BIG;
    #pragma unroll
    for (int k = 0; k < K; k++) {
        int j = tid + k * TPB;
        float v2 = NEG_BIG;
        if (j < NN) {
            float lmit  = fminf(0.f, P_EXP * (__ldg(&g_lc[j]) - lc_l));
            float lcomp = fmaxf(0.f, Q_EXP * (xv[k] - base - ls));
            v2 = xv[k] + lmit + lcomp;             // == x at j == label-1
        }
        xv[k] = v2;
        m2 = fmaxf(m2, v2);
    }
    m2 = blockMax(m2, sh);

    float s2 = 0.f;
    #pragma unroll
    for (int k = 0; k < K; k++) {
        int j = tid + k * TPB;
        if (j < NN) s2 += __expf(xv[k] - m2);
    }
    float S2 = blockSum(s2, sh);

    if (tid == 0)
        g_row_out[row] = m2 + __logf(S2) - xl;     // LSE(x2) - x2[label]
}

// ---------------------------------------------------------------------------
__global__ void k_final(float* __restrict__ out) {
    __shared__ float shs[32];
    __shared__ int   shc[32];
    int tid = threadIdx.x;
    float s = 0.f;
    int   c = 0;
    for (int i = tid; i < BB; i += 1024) {
        s += g_row_out[i];
        c += (g_labels[i] != 0);
    }
    #pragma unroll
    for (int o = 16; o > 0; o >>= 1) {
        s += __shfl_xor_sync(0xffffffffu, s, o);
        c += __shfl_xor_sync(0xffffffffu, c, o);
    }
    if ((tid & 31) == 0) { shs[tid >> 5] = s; shc[tid >> 5] = c; }
    __syncthreads();
    if (tid < 32) {
        s = shs[tid];
        c = shc[tid];
        #pragma unroll
        for (int o = 16; o > 0; o >>= 1) {
            s += __shfl_xor_sync(0xffffffffu, s, o);
            c += __shfl_xor_sync(0xffffffffu, c, o);
        }
        if (tid == 0)
            out[0] = (c > 0) ? (s / (float)c) : 0.f;
    }
}

// ---------------------------------------------------------------------------
extern "C" void kernel_launch(void* const* d_in, const int* in_sizes, int n_in,
                              void* d_out, int out_size) {
    const float* x   = (const float*)d_in[0];   // input  [B, C]
    const float* t   = (const float*)d_in[1];   // target [B, C] (one-hot)
    const float* cum = (const float*)d_in[2];   // cum_samples [NN]
    (void)in_sizes; (void)n_in; (void)out_size;

    k_zero_hist<<<(NN + 255) / 256, 256>>>();
    k_labels<<<BB, TPB>>>(t);
    k_lc<<<(NN + 255) / 256, 256>>>(cum);
    k_row<<<BB, TPB>>>(x);
    k_final<<<1, 1024>>>((float*)d_out);
}

// round 4
// speedup vs baseline: 1.2314x; 1.2314x over previous
#include <cuda_runtime.h>

#define BB   8192
#define CC   2514
#define NN   2513      // number of foreground classes
#define TPB  256
#define P_EXP 0.8f
#define Q_EXP 2.0f
#define LOG_EPS -4.6051701859880914f   // log(0.01)
#define NEG_BIG -1e30f
#define TOTAL4 ((BB * CC) / 4)         // 5,148,672 float4 in target

__device__ int   g_hist[NN];
__device__ int   g_labels[BB];
__device__ __align__(8) float g_lcs[CC + 2];   // g_lcs[col] = P*log(cum_c[col-1]); [0]=0
__device__ float g_row_out[BB];

// ---------------------------------------------------------------------------
__global__ void k_zero_hist() {
    int i = blockIdx.x * blockDim.x + threadIdx.x;
    if (i < NN) g_hist[i] = 0;
}

// Flat one-hot scan: fast path is LDG.128 + 3 FMAX + 1 predicate.
// Every row has exactly one positive, so g_labels needs no init.
__global__ void k_labels(const float4* __restrict__ t) {
    int idx    = blockIdx.x * blockDim.x + threadIdx.x;
    int stride = gridDim.x * blockDim.x;
    for (int i = idx; i < TOTAL4; i += stride) {
        float4 v = __ldg(t + i);
        float mx = fmaxf(fmaxf(v.x, v.y), fmaxf(v.z, v.w));
        if (mx > 0.f) {
            // a float4 can straddle a row boundary (2514 % 4 != 0): check each lane
            float vv[4] = {v.x, v.y, v.z, v.w};
            #pragma unroll
            for (int e = 0; e < 4; e++) {
                if (vv[e] > 0.f) {
                    int flat = 4 * i + e;
                    int row  = flat / CC;
                    int col  = flat - row * CC;
                    g_labels[row] = col;
                    if (col > 0) atomicAdd(&g_hist[col - 1], 1);
                }
            }
        }
    }
}

// g_lcs[col] = P * log(max(cum_samples[col-1] + count[col-1], 1)),  g_lcs[0] = 0
__global__ void k_lc(const float* __restrict__ cum_samples) {
    int i = blockIdx.x * blockDim.x + threadIdx.x;
    if (i == 0) { g_lcs[0] = 0.f; g_lcs[CC] = 0.f; g_lcs[CC + 1] = 0.f; }
    if (i < NN) {
        float c = cum_samples[i] + (float)g_hist[i];
        g_lcs[i + 1] = P_EXP * __logf(fmaxf(c, 1.0f));
    }
}

// ---------------------------------------------------------------------------
__device__ __forceinline__ float blockMax(float v, float* sh) {
    #pragma unroll
    for (int o = 16; o > 0; o >>= 1)
        v = fmaxf(v, __shfl_xor_sync(0xffffffffu, v, o));
    if ((threadIdx.x & 31) == 0) sh[threadIdx.x >> 5] = v;
    __syncthreads();
    if (threadIdx.x < 32) {
        float r = (threadIdx.x < (TPB / 32)) ? sh[threadIdx.x] : NEG_BIG;
        #pragma unroll
        for (int o = 4; o > 0; o >>= 1)
            r = fmaxf(r, __shfl_xor_sync(0xffffffffu, r, o));
        if (threadIdx.x == 0) sh[0] = r;
    }
    __syncthreads();
    float r = sh[0];
    __syncthreads();
    return r;
}

__device__ __forceinline__ float blockSum(float v, float* sh) {
    #pragma unroll
    for (int o = 16; o > 0; o >>= 1)
        v += __shfl_xor_sync(0xffffffffu, v, o);
    if ((threadIdx.x & 31) == 0) sh[threadIdx.x >> 5] = v;
    __syncthreads();
    if (threadIdx.x < 32) {
        float r = (threadIdx.x < (TPB / 32)) ? sh[threadIdx.x] : 0.f;
        #pragma unroll
        for (int o = 4; o > 0; o >>= 1)
            r += __shfl_xor_sync(0xffffffffu, r, o);
        if (threadIdx.x == 0) sh[0] = r;
    }
    __syncthreads();
    float r = sh[0];
    __syncthreads();
    return r;
}

// One block per row. 3 register passes, 3 block reductions.
// Key bound: lcomp <= Q*(-LOG_EPS) = 9.2 and lmit in [-P*log(1000), 0], so
// exp(x2 - m) with the FIRST-pass max m never overflows -> no second max pass.
__global__ void __launch_bounds__(TPB) k_row(const float* __restrict__ x) {
    const int row = blockIdx.x;
    const int tid = threadIdx.x;

    const int label = g_labels[row];
    if (label == 0) {                      // background row: excluded from loss
        if (tid == 0) g_row_out[row] = 0.f;
        return;
    }

    __shared__ float sh[8];

    // full row including col 0 (masked) -> float2-aligned: 2514*4 % 8 == 0
    const float2* p   = reinterpret_cast<const float2*>(x + (size_t)row * CC);
    const float2* plc = reinterpret_cast<const float2*>(g_lcs);
    const float   plc_l = g_lcs[label];    // P * log(cum_c at positive class)

    const int NF2 = CC / 2;                // 1257 float2 per row
    float2 xv[5];
    float2 lm[5];

    // --- pass 1: load x and P*lc, compute lmit, track max(x) ---
    float m = NEG_BIG;
    #pragma unroll
    for (int k = 0; k < 5; k++) {
        int i = tid + k * TPB;
        if (k < 4 || i < NF2) {
            float2 v = __ldg(p + i);
            float2 l = __ldg(plc + i);
            lm[k].x = fminf(0.f, l.x - plc_l);
            lm[k].y = fminf(0.f, l.y - plc_l);
            xv[k] = v;
            m = fmaxf(m, fmaxf(v.x, v.y));
        } else {
            xv[k].x = NEG_BIG; xv[k].y = NEG_BIG;
            lm[k].x = 0.f;     lm[k].y = 0.f;
        }
    }
    if (tid == 0) xv[0].x = NEG_BIG;       // mask background column 0
    if (tid == 0) m = fmaxf(xv[0].y, fmaxf(xv[1].x, m));  // cheap re-max w/o col0? (m may have included col0)
    // NOTE: m computed above may include col 0's x; recompute thread-0 max safely:
    if (tid == 0) {
        m = NEG_BIG;
        #pragma unroll
        for (int k = 0; k < 5; k++) m = fmaxf(m, fmaxf(xv[k].x, xv[k].y));
    }
    m = blockMax(m, sh);

    // --- pass 2: sum exp(x - m), shift xv in place ---
    float s = 0.f;
    #pragma unroll
    for (int k = 0; k < 5; k++) {
        xv[k].x -= m; xv[k].y -= m;
        s += __expf(xv[k].x) + __expf(xv[k].y);
    }
    float S = blockSum(s, sh);

    float base = m + __logf(S);                         // logsumexp(x)
    float xl   = __ldg(x + (size_t)row * CC + label);   // broadcast load
    float ls   = fmaxf(xl - base, LOG_EPS);             // log(max(self_score, EPS))
    float c2   = Q_EXP * (base + ls - m);               // xv now holds x - m

    // --- pass 3: x2 - m = (x-m) + lmit + relu(Q*(x-m) - c2); sum exp ---
    float s2 = 0.f;
    #pragma unroll
    for (int k = 0; k < 5; k++) {
        float vx = xv[k].x;
        float vy = xv[k].y;
        float tx = fmaxf(0.f, fmaf(Q_EXP, vx, -c2));
        float ty = fmaxf(0.f, fmaf(Q_EXP, vy, -c2));
        s2 += __expf(vx + lm[k].x + tx);
        s2 += __expf(vy + lm[k].y + ty);
    }
    float S2 = blockSum(s2, sh);

    if (tid == 0)
        g_row_out[row] = m + __logf(S2) - xl;           // LSE(x2) - x2[label]
}

// ---------------------------------------------------------------------------
__global__ void k_final(float* __restrict__ out) {
    __shared__ float shs[32];
    __shared__ int   shc[32];
    int tid = threadIdx.x;
    float s = 0.f;
    int   c = 0;
    for (int i = tid; i < BB; i += 1024) {
        s += g_row_out[i];
        c += (g_labels[i] != 0);
    }
    #pragma unroll
    for (int o = 16; o > 0; o >>= 1) {
        s += __shfl_xor_sync(0xffffffffu, s, o);
        c += __shfl_xor_sync(0xffffffffu, c, o);
    }
    if ((tid & 31) == 0) { shs[tid >> 5] = s; shc[tid >> 5] = c; }
    __syncthreads();
    if (tid < 32) {
        s = shs[tid];
        c = shc[tid];
        #pragma unroll
        for (int o = 16; o > 0; o >>= 1) {
            s += __shfl_xor_sync(0xffffffffu, s, o);
            c += __shfl_xor_sync(0xffffffffu, c, o);
        }
        if (tid == 0)
            out[0] = (c > 0) ? (s / (float)c) : 0.f;
    }
}

// ---------------------------------------------------------------------------
extern "C" void kernel_launch(void* const* d_in, const int* in_sizes, int n_in,
                              void* d_out, int out_size) {
    const float* x   = (const float*)d_in[0];   // input  [B, C]
    const float* t   = (const float*)d_in[1];   // target [B, C] (one-hot)
    const float* cum = (const float*)d_in[2];   // cum_samples [NN]
    (void)in_sizes; (void)n_in; (void)out_size;

    k_zero_hist<<<(NN + 255) / 256, 256>>>();
    k_labels<<<4096, 256>>>((const float4*)t);
    k_lc<<<(NN + 255) / 256, 256>>>(cum);
    k_row<<<BB, TPB>>>(x);
    k_final<<<1, 1024>>>((float*)d_out);
}

// round 5
// speedup vs baseline: 1.3340x; 1.0833x over previous
#include <cuda_runtime.h>

#define BB   8192
#define CC   2514
#define NN   2513      // number of foreground classes
#define TPB  256
#define P_EXP 0.8f
#define Q_EXP 2.0f
#define LOG_EPS -4.6051701859880914f   // log(0.01)
#define NEG_BIG -1e30f
#define TOTAL4 ((BB * CC) / 4)         // float4 count in target

__device__ int   g_hist[NN];
__device__ int   g_labels[BB];
__device__ __align__(8) float g_cp[CC + 2];  // g_cp[col] = cum_c[col-1]^P ; [0]=1
__device__ float g_row_out[BB];

// ---------------------------------------------------------------------------
__global__ void k_zero_hist() {
    int i = blockIdx.x * blockDim.x + threadIdx.x;
    if (i < NN) g_hist[i] = 0;
}

// Flat one-hot scan: fast path is LDG.128 + 3 FMAX + 1 predicate.
__global__ void k_labels(const float4* __restrict__ t) {
    int idx    = blockIdx.x * blockDim.x + threadIdx.x;
    int stride = gridDim.x * blockDim.x;
    for (int i = idx; i < TOTAL4; i += stride) {
        float4 v = __ldg(t + i);
        float mx = fmaxf(fmaxf(v.x, v.y), fmaxf(v.z, v.w));
        if (mx > 0.f) {
            float vv[4] = {v.x, v.y, v.z, v.w};
            #pragma unroll
            for (int e = 0; e < 4; e++) {
                if (vv[e] > 0.f) {
                    int flat = 4 * i + e;
                    int row  = flat / CC;
                    int col  = flat - row * CC;
                    g_labels[row] = col;
                    if (col > 0) atomicAdd(&g_hist[col - 1], 1);
                }
            }
        }
    }
}

// g_cp[col] = (max(cum_samples[col-1] + count[col-1], 1))^P, g_cp[0] = 1
__global__ void k_cp(const float* __restrict__ cum_samples) {
    int i = blockIdx.x * blockDim.x + threadIdx.x;
    if (i == 0) { g_cp[0] = 1.f; g_cp[CC] = 1.f; g_cp[CC + 1] = 1.f; }
    if (i < NN) {
        float c = fmaxf(cum_samples[i] + (float)g_hist[i], 1.0f);
        g_cp[i + 1] = __expf(P_EXP * __logf(c));
    }
}

// ---------------------------------------------------------------------------
__device__ __forceinline__ float blockMax(float v, float* sh) {
    #pragma unroll
    for (int o = 16; o > 0; o >>= 1)
        v = fmaxf(v, __shfl_xor_sync(0xffffffffu, v, o));
    if ((threadIdx.x & 31) == 0) sh[threadIdx.x >> 5] = v;
    __syncthreads();
    if (threadIdx.x < 32) {
        float r = (threadIdx.x < (TPB / 32)) ? sh[threadIdx.x] : NEG_BIG;
        #pragma unroll
        for (int o = 4; o > 0; o >>= 1)
            r = fmaxf(r, __shfl_xor_sync(0xffffffffu, r, o));
        if (threadIdx.x == 0) sh[0] = r;
    }
    __syncthreads();
    float r = sh[0];
    __syncthreads();
    return r;
}

__device__ __forceinline__ float blockSum(float v, float* sh) {
    #pragma unroll
    for (int o = 16; o > 0; o >>= 1)
        v += __shfl_xor_sync(0xffffffffu, v, o);
    if ((threadIdx.x & 31) == 0) sh[threadIdx.x >> 5] = v;
    __syncthreads();
    if (threadIdx.x < 32) {
        float r = (threadIdx.x < (TPB / 32)) ? sh[threadIdx.x] : 0.f;
        #pragma unroll
        for (int o = 4; o > 0; o >>= 1)
            r += __shfl_xor_sync(0xffffffffu, r, o);
        if (threadIdx.x == 0) sh[0] = r;
    }
    __syncthreads();
    float r = sh[0];
    __syncthreads();
    return r;
}

// One block per row. Linear-domain seesaw:
//   exp(x2 - m) = e * mit * comp,  e = exp(x - m)
//   mit  = min(1, cp[j] / cp[label])        (cp = cum_c^P precomputed)
//   comp = max(1, e*e*K),  K = exp(-2*(logS + ls))   (Q == 2)
// Masked lanes carry x = NEG_BIG -> e = 0 -> contribute 0 to both sums.
__global__ void __launch_bounds__(TPB, 8) k_row(const float* __restrict__ x) {
    const int row = blockIdx.x;
    const int tid = threadIdx.x;

    const int label = g_labels[row];
    if (label == 0) {                      // background row: excluded from loss
        if (tid == 0) g_row_out[row] = 0.f;
        return;
    }

    __shared__ float sh[8];

    // full row including col 0 (masked); rows are 8B-aligned (2514*4 % 8 == 0)
    const float2* p  = reinterpret_cast<const float2*>(x + (size_t)row * CC);
    const float2* pc = reinterpret_cast<const float2*>(g_cp);

    const int NF2 = CC / 2;                // 1257 float2 per row
    float2 xv[5];

    // --- pass 1: load x, mask, track max ---
    float m = NEG_BIG;
    #pragma unroll
    for (int k = 0; k < 5; k++) {
        int i = tid + k * TPB;
        if (k < 4 || i < NF2) {
            float2 v = __ldg(p + i);
            if (k == 0 && tid == 0) v.x = NEG_BIG;   // background column 0
            xv[k] = v;
            m = fmaxf(m, fmaxf(v.x, v.y));
        } else {
            xv[k].x = NEG_BIG; xv[k].y = NEG_BIG;
        }
    }
    m = blockMax(m, sh);

    // --- pass 2: e = exp(x - m) in place, sum ---
    float s = 0.f;
    #pragma unroll
    for (int k = 0; k < 5; k++) {
        xv[k].x = __expf(xv[k].x - m);
        xv[k].y = __expf(xv[k].y - m);
        s += xv[k].x + xv[k].y;
    }
    float S = blockSum(s, sh);

    // per-row scalars (redundantly per thread; all broadcast loads)
    float logS  = __logf(S);
    float xl    = __ldg(x + (size_t)row * CC + label);
    float ls    = fmaxf(xl - m - logS, LOG_EPS);       // log(max(self_score, EPS))
    float K     = __expf(-2.f * (logS + ls));
    float rcp_l = 1.f / __ldg(&g_cp[label]);

    // --- pass 3: s2 += e * mit * comp  (pure FMA pipe, cp from L1) ---
    float s2 = 0.f;
    #pragma unroll
    for (int k = 0; k < 5; k++) {
        int i = tid + k * TPB;
        if (k < 4 || i < NF2) {
            float2 cp = __ldg(pc + i);
            float ex = xv[k].x, ey = xv[k].y;
            float mitx = fminf(1.f, cp.x * rcp_l);
            float mity = fminf(1.f, cp.y * rcp_l);
            float cmx  = fmaxf(1.f, ex * ex * K);
            float cmy  = fmaxf(1.f, ey * ey * K);
            s2 += ex * mitx * cmx + ey * mity * cmy;
        }
    }
    float S2 = blockSum(s2, sh);

    if (tid == 0)
        g_row_out[row] = m + __logf(S2) - xl;          // LSE(x2) - x2[label]
}

// ---------------------------------------------------------------------------
__global__ void k_final(float* __restrict__ out) {
    __shared__ float shs[32];
    __shared__ int   shc[32];
    int tid = threadIdx.x;
    float s = 0.f;
    int   c = 0;
    for (int i = tid; i < BB; i += 1024) {
        s += g_row_out[i];
        c += (g_labels[i] != 0);
    }
    #pragma unroll
    for (int o = 16; o > 0; o >>= 1) {
        s += __shfl_xor_sync(0xffffffffu, s, o);
        c += __shfl_xor_sync(0xffffffffu, c, o);
    }
    if ((tid & 31) == 0) { shs[tid >> 5] = s; shc[tid >> 5] = c; }
    __syncthreads();
    if (tid < 32) {
        s = shs[tid];
        c = shc[tid];
        #pragma unroll
        for (int o = 16; o > 0; o >>= 1) {
            s += __shfl_xor_sync(0xffffffffu, s, o);
            c += __shfl_xor_sync(0xffffffffu, c, o);
        }
        if (tid == 0)
            out[0] = (c > 0) ? (s / (float)c) : 0.f;
    }
}

// ---------------------------------------------------------------------------
extern "C" void kernel_launch(void* const* d_in, const int* in_sizes, int n_in,
                              void* d_out, int out_size) {
    const float* x   = (const float*)d_in[0];   // input  [B, C]
    const float* t   = (const float*)d_in[1];   // target [B, C] (one-hot)
    const float* cum = (const float*)d_in[2];   // cum_samples [NN]
    (void)in_sizes; (void)n_in; (void)out_size;

    k_zero_hist<<<(NN + 255) / 256, 256>>>();
    k_labels<<<4096, 256>>>((const float4*)t);
    k_cp<<<(NN + 255) / 256, 256>>>(cum);
    k_row<<<BB, TPB>>>(x);
    k_final<<<1, 1024>>>((float*)d_out);
}